// round 1
// baseline (speedup 1.0000x reference)
#include <cuda_runtime.h>
#include <cuda_bf16.h>

// Problem constants
#define BB   64      // batch (inputs)
#define MM   256     // modes
#define KK   4096    // spatial (64*64)

#define KC      128  // K per CTA chunk
#define KSPLIT  32   // KK / KC
#define MT      32   // modes per CTA
#define MTILES  8    // MM / MT
#define EPS_C   0.0009f

// Deterministic partial buffers (no cudaMalloc allowed)
__device__ float g_dot[KSPLIT * BB * MM];   // [s][b][m]  2 MB
__device__ float g_fss[KSPLIT * BB];        // [s][b]
__device__ float g_mss[KSPLIT * MM];        // [s][m]

__device__ __forceinline__ unsigned long long fma2(unsigned long long a,
                                                   unsigned long long b,
                                                   unsigned long long c) {
    unsigned long long d;
    asm("fma.rn.f32x2 %0, %1, %2, %3;" : "=l"(d) : "l"(a), "l"(b), "l"(c));
    return d;
}

__device__ __forceinline__ float2 ull2f2(unsigned long long u) {
    float2 f;
    f.x = __uint_as_float((unsigned int)u);
    f.y = __uint_as_float((unsigned int)(u >> 32));
    return f;
}

// GEMM with K-split: CTA (mt, ks) computes dot[b=0..63][m=mt*32..+31] over k chunk ks.
// Also emits partial squared norms as byproducts of the staged tiles.
__global__ __launch_bounds__(256)
void gemm_partial_kernel(const float* __restrict__ inp,
                         const float* __restrict__ mds) {
    __shared__ float As[BB * KC];   // 32 KB, k-major, quad-swizzled
    __shared__ float Bs[MT * KC];   // 16 KB

    const int mt = blockIdx.x;
    const int ks = blockIdx.y;
    const int kbase = ks * KC;
    const int mbase = mt * MT;
    const int tid = threadIdx.x;

    float4* As4 = reinterpret_cast<float4*>(As);
    float4* Bs4 = reinterpret_cast<float4*>(Bs);

    // ---- load A tile: 64 rows x 128 k = 2048 float4, 8 per thread (coalesced) ----
#pragma unroll
    for (int i = 0; i < 8; ++i) {
        int j  = i * 256 + tid;
        int b  = j >> 5;          // row
        int kq = j & 31;          // float4 within row
        float4 v = *(reinterpret_cast<const float4*>(inp + (size_t)b * KK + kbase) + kq);
        As4[b * 32 + (kq ^ ((b >> 2) & 7))] = v;
    }
    // ---- load B tile: 32 rows x 128 k = 1024 float4, 4 per thread ----
#pragma unroll
    for (int i = 0; i < 4; ++i) {
        int j  = i * 256 + tid;
        int m  = j >> 5;
        int kq = j & 31;
        float4 v = *(reinterpret_cast<const float4*>(mds + (size_t)(mbase + m) * KK + kbase) + kq);
        Bs4[m * 32 + (kq ^ ((m >> 2) & 7))] = v;
    }
    __syncthreads();

    // ---- partial squared norms from staged tiles ----
    if (mt == 0 && tid < 64) {          // warps 0-1: input norms
        int b = tid;
        int sw = (b >> 2) & 7;
        float s = 0.f;
#pragma unroll
        for (int kq = 0; kq < 32; ++kq) {
            float4 v = As4[b * 32 + (kq ^ sw)];
            s += v.x * v.x + v.y * v.y + v.z * v.z + v.w * v.w;
        }
        g_fss[ks * BB + b] = s;
    }
    if (tid >= 64 && tid < 96) {        // warp 2: mode norms (this CTA's slice)
        int m = tid - 64;
        int sw = (m >> 2) & 7;
        float s = 0.f;
#pragma unroll
        for (int kq = 0; kq < 32; ++kq) {
            float4 v = Bs4[m * 32 + (kq ^ sw)];
            s += v.x * v.x + v.y * v.y + v.z * v.z + v.w * v.w;
        }
        g_mss[ks * MM + mbase + m] = s;
    }

    // ---- main loop: 4b x 2m micro-tile, packed f32x2 over k-pairs ----
    const int tm = tid & 15;   // m0 = 2*tm  (lanes vary tm -> coalesced epilogue)
    const int tb = tid >> 4;   // b0 = 4*tb
    const int sa = tb & 7;            // (b>>2)&7 for b = 4tb+bb
    const int sb = (tm >> 1) & 7;     // (m>>2)&7 for m = 2tm+mm

    unsigned long long acc[4][2];
#pragma unroll
    for (int i = 0; i < 4; ++i) { acc[i][0] = 0ull; acc[i][1] = 0ull; }

    const ulonglong2* As2 = reinterpret_cast<const ulonglong2*>(As);
    const ulonglong2* Bs2 = reinterpret_cast<const ulonglong2*>(Bs);

#pragma unroll 8
    for (int kq = 0; kq < 32; ++kq) {
        ulonglong2 a[4];
        ulonglong2 bv[2];
#pragma unroll
        for (int bb = 0; bb < 4; ++bb)
            a[bb] = As2[(4 * tb + bb) * 32 + (kq ^ sa)];
#pragma unroll
        for (int mm = 0; mm < 2; ++mm)
            bv[mm] = Bs2[(2 * tm + mm) * 32 + (kq ^ sb)];
#pragma unroll
        for (int bb = 0; bb < 4; ++bb)
#pragma unroll
            for (int mm = 0; mm < 2; ++mm) {
                acc[bb][mm] = fma2(a[bb].x, bv[mm].x, acc[bb][mm]);
                acc[bb][mm] = fma2(a[bb].y, bv[mm].y, acc[bb][mm]);
            }
    }

    // ---- epilogue: reduce even/odd lanes, write float2 (coalesced over tm) ----
#pragma unroll
    for (int bb = 0; bb < 4; ++bb) {
        int b = 4 * tb + bb;
        float2 e0 = ull2f2(acc[bb][0]);
        float2 e1 = ull2f2(acc[bb][1]);
        float2 r;
        r.x = e0.x + e0.y;
        r.y = e1.x + e1.y;
        *reinterpret_cast<float2*>(&g_dot[((size_t)ks * BB + b) * MM + mbase + 2 * tm]) = r;
    }
}

// Finalize: sum K-split partials, apply metric, min over m. One block per b.
__global__ __launch_bounds__(256)
void finalize_kernel(float* __restrict__ out) {
    const int b = blockIdx.x;
    const int m = threadIdx.x;   // 256 modes

    float dot = 0.f, mss = 0.f, fss = 0.f;
#pragma unroll 8
    for (int s = 0; s < KSPLIT; ++s) {
        dot += g_dot[((size_t)s * BB + b) * MM + m];
        mss += g_mss[s * MM + m];
        fss += g_fss[s * BB + b];
    }

    float fn = sqrtf(fss);
    float mn = sqrtf(mss);
    float c  = dot / (fn * mn);
    float dn = sqrtf(fmaxf(2.f - 2.f * c, 0.f));
    float lum = (2.f * fn * mn + EPS_C) / (fss + mss + EPS_C);
    float metric = (1.f - (2.f - dn) * 0.5f * sqrtf(lum)) * 2.f;

    // min-reduce over 256 threads
#pragma unroll
    for (int off = 16; off > 0; off >>= 1)
        metric = fminf(metric, __shfl_xor_sync(0xffffffffu, metric, off));

    __shared__ float red[8];
    int wid = threadIdx.x >> 5;
    int lane = threadIdx.x & 31;
    if (lane == 0) red[wid] = metric;
    __syncthreads();
    if (threadIdx.x == 0) {
        float v = red[0];
#pragma unroll
        for (int w = 1; w < 8; ++w) v = fminf(v, red[w]);
        out[b] = v;
    }
}

extern "C" void kernel_launch(void* const* d_in, const int* in_sizes, int n_in,
                              void* d_out, int out_size) {
    const float* inp = (const float*)d_in[0];
    const float* mds = (const float*)d_in[1];
    // Defensive: identify tensors by element count (inputs=262144, modes=1048576)
    if (in_sizes[0] > in_sizes[1]) {
        const float* t = inp; inp = mds; mds = t;
    }

    dim3 grid(MTILES, KSPLIT);
    gemm_partial_kernel<<<grid, 256>>>(inp, mds);
    finalize_kernel<<<BB, 256>>>((float*)d_out);
}

// round 2
// speedup vs baseline: 1.2542x; 1.2542x over previous
#include <cuda_runtime.h>
#include <cuda_bf16.h>

// Problem constants
#define BB   64      // batch (inputs)
#define MM   256     // modes
#define KK   4096    // spatial (64*64)

#define KC      128  // K per CTA chunk
#define KSPLIT  32   // KK / KC
#define MT      32   // modes per CTA (one per lane)
#define MTILES  8    // MM / MT
#define EPS_C   0.0009f

// Deterministic partial buffers (no cudaMalloc allowed)
__device__ float g_dot[KSPLIT * BB * MM];   // [s][b][m]  2 MB
__device__ float g_fss[KSPLIT * BB];        // [s][b]
__device__ float g_mss[KSPLIT * MM];        // [s][m]

__device__ __forceinline__ unsigned long long fma2(unsigned long long a,
                                                   unsigned long long b,
                                                   unsigned long long c) {
    unsigned long long d;
    asm("fma.rn.f32x2 %0, %1, %2, %3;" : "=l"(d) : "l"(a), "l"(b), "l"(c));
    return d;
}

__device__ __forceinline__ float2 ull2f2(unsigned long long u) {
    float2 f;
    f.x = __uint_as_float((unsigned int)u);
    f.y = __uint_as_float((unsigned int)(u >> 32));
    return f;
}

// GEMM with K-split. CTA (mt, ks): dot[b=0..63][m = mt*32 .. +31] over k-chunk ks.
// Micro-tile: warp w owns b-rows 8w..8w+7 (A reads are warp-broadcast -> ~0
// crossbar bytes); lane owns one m (B reads swizzled -> 4-phase floor).
__global__ __launch_bounds__(256, 2)
void gemm_partial_kernel(const float* __restrict__ inp,
                         const float* __restrict__ mds) {
    __shared__ float As[BB * KC];   // 32 KB, k-major, unswizzled
    __shared__ float Bs[MT * KC];   // 16 KB, k-major, kq ^ (m&7) swizzle

    const int mt = blockIdx.x;
    const int ks = blockIdx.y;
    const int kbase = ks * KC;
    const int mbase = mt * MT;
    const int tid  = threadIdx.x;
    const int lane = tid & 31;
    const int w    = tid >> 5;

    float4* As4 = reinterpret_cast<float4*>(As);
    float4* Bs4 = reinterpret_cast<float4*>(Bs);

    // ---- stage A: 64 rows x 32 float4, coalesced, no swizzle ----
#pragma unroll
    for (int i = 0; i < 8; ++i) {
        int j  = i * 256 + tid;
        int b  = j >> 5;
        int kq = j & 31;
        As4[b * 32 + kq] =
            *(reinterpret_cast<const float4*>(inp + (size_t)b * KK + kbase) + kq);
    }
    // ---- stage B: 32 rows x 32 float4, swizzled ----
#pragma unroll
    for (int i = 0; i < 4; ++i) {
        int j  = i * 256 + tid;
        int m  = j >> 5;
        int kq = j & 31;
        Bs4[m * 32 + (kq ^ (m & 7))] =
            *(reinterpret_cast<const float4*>(mds + (size_t)(mbase + m) * KK + kbase) + kq);
    }
    __syncthreads();

    // ---- main loop: lane's m fixed, 8 b-rows per warp, f32x2 over k-pairs ----
    const int c = lane & 7;                     // B swizzle constant for m = lane
    const ulonglong2* As2 = reinterpret_cast<const ulonglong2*>(As);
    const ulonglong2* Bs2 = reinterpret_cast<const ulonglong2*>(Bs);

    unsigned long long acc[8];
#pragma unroll
    for (int r = 0; r < 8; ++r) acc[r] = 0ull;

#pragma unroll 4
    for (int kq = 0; kq < 32; ++kq) {
        ulonglong2 bv = Bs2[lane * 32 + (kq ^ c)];    // lane-distinct, 4-phase floor
#pragma unroll
        for (int r = 0; r < 8; ++r) {
            ulonglong2 av = As2[(8 * w + r) * 32 + kq]; // warp-broadcast
            acc[r] = fma2(av.x, bv.x, acc[r]);
            acc[r] = fma2(av.y, bv.y, acc[r]);
        }
    }

    // ---- epilogue: reduce k-parity lanes, coalesced store ----
#pragma unroll
    for (int r = 0; r < 8; ++r) {
        float2 e = ull2f2(acc[r]);
        g_dot[((size_t)ks * BB + 8 * w + r) * MM + mbase + lane] = e.x + e.y;
    }

    // ---- partial squared norms (conflict-free lane-indexed reads + shfl) ----
    // mode norms: warp w handles m-rows 4w..4w+3 of this CTA's slice
#pragma unroll
    for (int r = 0; r < 4; ++r) {
        int m = 4 * w + r;
        float4 v = Bs4[m * 32 + (lane ^ (m & 7))];
        float s = v.x * v.x + v.y * v.y + v.z * v.z + v.w * v.w;
#pragma unroll
        for (int o = 16; o > 0; o >>= 1) s += __shfl_xor_sync(0xffffffffu, s, o);
        if (lane == 0) g_mss[ks * MM + mbase + m] = s;
    }
    // input norms: only mt==0 column; warp w handles b-rows 8w..8w+7
    if (mt == 0) {
#pragma unroll
        for (int r = 0; r < 8; ++r) {
            int b = 8 * w + r;
            float4 v = As4[b * 32 + lane];
            float s = v.x * v.x + v.y * v.y + v.z * v.z + v.w * v.w;
#pragma unroll
            for (int o = 16; o > 0; o >>= 1) s += __shfl_xor_sync(0xffffffffu, s, o);
            if (lane == 0) g_fss[ks * BB + b] = s;
        }
    }
}

// Finalize: grid=64 (one block per b), 1024 threads = (m, s-quarter).
// Each thread sums 8 split-partials (fully unrolled -> high MLP), 4-way smem
// combine, then metric + min over m.
__global__ __launch_bounds__(1024)
void finalize_kernel(float* __restrict__ out) {
    __shared__ float sd[4][MM];
    __shared__ float sm_[4][MM];
    __shared__ float sf[4];
    __shared__ float red[8];

    const int b  = blockIdx.x;
    const int m  = threadIdx.x & 255;
    const int sq = threadIdx.x >> 8;   // 0..3

    float dot = 0.f, mss = 0.f, fss = 0.f;
#pragma unroll
    for (int i = 0; i < 8; ++i) {
        int s = sq * 8 + i;
        dot += g_dot[((size_t)s * BB + b) * MM + m];
        mss += g_mss[s * MM + m];
        fss += g_fss[s * BB + b];
    }
    sd[sq][m]  = dot;
    sm_[sq][m] = mss;
    if (m == 0) sf[sq] = fss;
    __syncthreads();

    if (sq == 0) {
        dot = sd[0][m] + sd[1][m] + sd[2][m] + sd[3][m];
        mss = sm_[0][m] + sm_[1][m] + sm_[2][m] + sm_[3][m];
        fss = sf[0] + sf[1] + sf[2] + sf[3];

        float fn = sqrtf(fss);
        float mn = sqrtf(mss);
        float cc = dot / (fn * mn);
        float dn = sqrtf(fmaxf(2.f - 2.f * cc, 0.f));
        float lum = (2.f * fn * mn + EPS_C) / (fss + mss + EPS_C);
        float metric = (1.f - (2.f - dn) * 0.5f * sqrtf(lum)) * 2.f;

#pragma unroll
        for (int o = 16; o > 0; o >>= 1)
            metric = fminf(metric, __shfl_xor_sync(0xffffffffu, metric, o));
        if ((m & 31) == 0) red[m >> 5] = metric;
    }
    __syncthreads();
    if (threadIdx.x == 0) {
        float v = red[0];
#pragma unroll
        for (int i = 1; i < 8; ++i) v = fminf(v, red[i]);
        out[b] = v;
    }
}

extern "C" void kernel_launch(void* const* d_in, const int* in_sizes, int n_in,
                              void* d_out, int out_size) {
    const float* inp = (const float*)d_in[0];
    const float* mds = (const float*)d_in[1];
    if (in_sizes[0] > in_sizes[1]) {   // identify by element count
        const float* t = inp; inp = mds; mds = t;
    }

    dim3 grid(MTILES, KSPLIT);
    gemm_partial_kernel<<<grid, 256>>>(inp, mds);
    finalize_kernel<<<BB, 1024>>>((float*)d_out);
}